// round 6
// baseline (speedup 1.0000x reference)
#include <cuda_runtime.h>
#include <cuda_bf16.h>
#include <cuda_fp8.h>

#define NN 8192
#define TEMPER 0.2f

// Scratch (static __device__ arrays per harness rules)
static __device__ unsigned char g_Q8[(size_t)NN * NN];  // 64 MB fp8 e4m3 Q
static __device__ float g_colAccS[4][NN];               // sliced accumulators
static __device__ float g_V[NN];
static __device__ float g_U[NN];
static __device__ double g_sum;
static __device__ double g_sumsq;
static __device__ float g_kscale;
static __device__ unsigned int g_redCount;

// ---------------------------------------------------------------- helpers
__device__ __forceinline__ float2 f8x2_to_f2(unsigned int s) {
    __half2_raw hr = __nv_cvt_fp8x2_to_halfraw2((__nv_fp8x2_storage_t)s, __NV_E4M3);
    return __half22float2(*reinterpret_cast<__half2*>(&hr));
}

// decode 8 fp8 (uint2) and fma against 8 V floats into acc
__device__ __forceinline__ float fma8(uint2 w, float4 v0, float4 v1, float acc) {
    float2 lo0 = f8x2_to_f2(w.x & 0xffffu);
    float2 hi0 = f8x2_to_f2(w.x >> 16);
    float2 lo1 = f8x2_to_f2(w.y & 0xffffu);
    float2 hi1 = f8x2_to_f2(w.y >> 16);
    acc = fmaf(lo0.x, v0.x, acc);
    acc = fmaf(lo0.y, v0.y, acc);
    acc = fmaf(hi0.x, v0.z, acc);
    acc = fmaf(hi0.y, v0.w, acc);
    acc = fmaf(lo1.x, v1.x, acc);
    acc = fmaf(lo1.y, v1.y, acc);
    acc = fmaf(hi1.x, v1.z, acc);
    acc = fmaf(hi1.y, v1.w, acc);
    return acc;
}

// ---------------------------------------------------------------- init
__global__ void k_init() {
    int i = blockIdx.x * blockDim.x + threadIdx.x;
    if (i < NN) {
        g_colAccS[0][i] = 0.0f;
        g_colAccS[1][i] = 0.0f;
        g_colAccS[2][i] = 0.0f;
        g_colAccS[3][i] = 0.0f;
    }
    if (i == 0) {
        g_sum = 0.0;
        g_sumsq = 0.0;
        g_redCount = 0u;
    }
}

// ---------------------------------------------------------------- reduce: sum / sumsq (+ fused scalar finalize)
__global__ void __launch_bounds__(256) k_reduce(const float* __restrict__ c) {
    const size_t total4 = (size_t)NN * NN / 4;
    const size_t stride = (size_t)gridDim.x * blockDim.x;
    double s = 0.0, ss = 0.0;
    for (size_t i = (size_t)blockIdx.x * blockDim.x + threadIdx.x; i < total4; i += stride) {
        float4 v = reinterpret_cast<const float4*>(c)[i];
        float cs  = (v.x + v.y) + (v.z + v.w);
        float css = fmaf(v.x, v.x, fmaf(v.y, v.y, fmaf(v.z, v.z, v.w * v.w)));
        s  += (double)cs;
        ss += (double)css;
    }
    for (int o = 16; o > 0; o >>= 1) {
        s  += __shfl_down_sync(0xffffffffu, s, o);
        ss += __shfl_down_sync(0xffffffffu, ss, o);
    }
    __shared__ double sh_s[8], sh_ss[8];
    int warp = threadIdx.x >> 5, lane = threadIdx.x & 31;
    if (lane == 0) { sh_s[warp] = s; sh_ss[warp] = ss; }
    __syncthreads();
    if (threadIdx.x < 8) {
        s = sh_s[threadIdx.x]; ss = sh_ss[threadIdx.x];
        for (int o = 4; o > 0; o >>= 1) {
            s  += __shfl_down_sync(0xffu, s, o);
            ss += __shfl_down_sync(0xffu, ss, o);
        }
        if (threadIdx.x == 0) {
            atomicAdd(&g_sum, s);
            atomicAdd(&g_sumsq, ss);
            __threadfence();
            unsigned int done = atomicAdd(&g_redCount, 1u);
            if (done == gridDim.x - 1) {
                double n = (double)NN * (double)NN;
                double S  = *(volatile double*)&g_sum;
                double SS = *(volatile double*)&g_sumsq;
                double var = (SS - S * S / n) / (n - 1.0);
                g_kscale = 1.0f / ((float)sqrt(var) * TEMPER);
            }
        }
    }
}

// ---------------------------------------------------------------- build Q8 (fp8) + exact colsum
// grid (8, 128): x = 1024-col chunk, y = 64-row chunk; 4 cols/thread
__global__ void __launch_bounds__(256) k_build8(const float* __restrict__ c) {
    const float kk = g_kscale;
    int col0 = (blockIdx.x * 256 + threadIdx.x) * 4;
    int row0 = blockIdx.y * 64;
    float a0 = 0.f, a1 = 0.f, a2 = 0.f, a3 = 0.f;
    for (int r = 0; r < 64; ++r) {
        size_t base = (size_t)(row0 + r) * NN + col0;
        float4 v = *reinterpret_cast<const float4*>(c + base);
        float q0 = __expf(-v.x * kk);
        float q1 = __expf(-v.y * kk);
        float q2 = __expf(-v.z * kk);
        float q3 = __expf(-v.w * kk);
        a0 += q0; a1 += q1; a2 += q2; a3 += q3;
        float2 p0; p0.x = q0; p0.y = q1;
        float2 p1; p1.x = q2; p1.y = q3;
        unsigned int lo = __nv_cvt_float2_to_fp8x2(p0, __NV_SATFINITE, __NV_E4M3);
        unsigned int hi = __nv_cvt_float2_to_fp8x2(p1, __NV_SATFINITE, __NV_E4M3);
        *reinterpret_cast<unsigned int*>(g_Q8 + base) = (hi << 16) | (lo & 0xffffu);
    }
    float* ca = g_colAccS[blockIdx.y & 3];
    atomicAdd(&ca[col0 + 0], a0);
    atomicAdd(&ca[col0 + 1], a1);
    atomicAdd(&ca[col0 + 2], a2);
    atomicAdd(&ca[col0 + 3], a3);
}

// ---------------------------------------------------------------- V = B / sum(slices) ; slices = 0
__global__ void k_vfin(const float* __restrict__ B) {
    int j = blockIdx.x * blockDim.x + threadIdx.x;
    if (j < NN) {
        float s = (g_colAccS[0][j] + g_colAccS[1][j]) + (g_colAccS[2][j] + g_colAccS[3][j]);
        g_V[j] = B[j] / s;
        g_colAccS[0][j] = 0.0f;
        g_colAccS[1][j] = 0.0f;
        g_colAccS[2][j] = 0.0f;
        g_colAccS[3][j] = 0.0f;
    }
}

// ---------------------------------------------------------------- U = A / (Q8 V)
// 512 blocks x 256 threads; warp handles 2 rows (shared V); uint2 loads (8 fp8/thread/step)
__global__ void __launch_bounds__(256) k_rowmv8(const float* __restrict__ A) {
    __shared__ float sV[NN];
    int tid = threadIdx.x;
#pragma unroll
    for (int i = 0; i < 8; ++i)
        reinterpret_cast<float4*>(sV)[tid + i * 256] =
            reinterpret_cast<const float4*>(g_V)[tid + i * 256];
    __syncthreads();
    int warp = tid >> 5, lane = tid & 31;
    int row0 = blockIdx.x * 16 + warp * 2;
    const uint2* q0 = reinterpret_cast<const uint2*>(g_Q8 + (size_t)row0 * NN);
    const uint2* q1 = reinterpret_cast<const uint2*>(g_Q8 + (size_t)(row0 + 1) * NN);
    const float4* v4 = reinterpret_cast<const float4*>(sV);
    float acc0 = 0.f, acc1 = 0.f;
    // 8192 cols / (8 per uint2 * 32 lanes) = 32 steps; batch 4 steps x 2 rows = 8x8B in flight
#pragma unroll
    for (int s = 0; s < 32; s += 4) {
        uint2 a[4], b[4];
#pragma unroll
        for (int u = 0; u < 4; ++u) {
            a[u] = q0[lane + (s + u) * 32];
            b[u] = q1[lane + (s + u) * 32];
        }
#pragma unroll
        for (int u = 0; u < 4; ++u) {
            int vi = lane * 2 + (s + u) * 64;
            float4 v0 = v4[vi];
            float4 v1 = v4[vi + 1];
            acc0 = fma8(a[u], v0, v1, acc0);
            acc1 = fma8(b[u], v0, v1, acc1);
        }
    }
    for (int o = 16; o > 0; o >>= 1) {
        acc0 += __shfl_down_sync(0xffffffffu, acc0, o);
        acc1 += __shfl_down_sync(0xffffffffu, acc1, o);
    }
    if (lane == 0) {
        g_U[row0]     = __ldg(A + row0) / acc0;
        g_U[row0 + 1] = __ldg(A + row0 + 1) / acc1;
    }
}

// ---------------------------------------------------------------- slices += Q8^T U
// grid 512: 128 row-chunks (64 rows) x 4 col-chunks (2048 cols); 8 cols/thread (uint2)
__global__ void __launch_bounds__(256) k_colmv8() {
    __shared__ float sU[64];
    int tid = threadIdx.x;
    int rb = blockIdx.x >> 2;
    int col0 = (blockIdx.x & 3) * 2048 + tid * 8;
    int row0 = rb * 64;
    if (tid < 64) sU[tid] = g_U[row0 + tid];
    __syncthreads();
    const uint2* qp = reinterpret_cast<const uint2*>(g_Q8 + (size_t)row0 * NN + col0);
    float a0 = 0.f, a1 = 0.f, a2 = 0.f, a3 = 0.f;
    float a4 = 0.f, a5 = 0.f, a6 = 0.f, a7 = 0.f;
#pragma unroll 8
    for (int r = 0; r < 64; ++r) {
        uint2 w = qp[(size_t)r * (NN / 8)];
        float u = sU[r];
        float2 lo0 = f8x2_to_f2(w.x & 0xffffu);
        float2 hi0 = f8x2_to_f2(w.x >> 16);
        float2 lo1 = f8x2_to_f2(w.y & 0xffffu);
        float2 hi1 = f8x2_to_f2(w.y >> 16);
        a0 = fmaf(lo0.x, u, a0);
        a1 = fmaf(lo0.y, u, a1);
        a2 = fmaf(hi0.x, u, a2);
        a3 = fmaf(hi0.y, u, a3);
        a4 = fmaf(lo1.x, u, a4);
        a5 = fmaf(lo1.y, u, a5);
        a6 = fmaf(hi1.x, u, a6);
        a7 = fmaf(hi1.y, u, a7);
    }
    float* ca = g_colAccS[rb & 3];
    atomicAdd(&ca[col0 + 0], a0);
    atomicAdd(&ca[col0 + 1], a1);
    atomicAdd(&ca[col0 + 2], a2);
    atomicAdd(&ca[col0 + 3], a3);
    atomicAdd(&ca[col0 + 4], a4);
    atomicAdd(&ca[col0 + 5], a5);
    atomicAdd(&ca[col0 + 6], a6);
    atomicAdd(&ca[col0 + 7], a7);
}

// ---------------------------------------------------------------- exact colmv (for V10): slices += Q^T U, Q from cdist
__global__ void __launch_bounds__(256) k_colmv_exact(const float* __restrict__ c) {
    __shared__ float sU[64];
    int tid = threadIdx.x;
    int rb = blockIdx.x >> 3;
    int col0 = (blockIdx.x & 7) * 1024 + tid * 4;
    int row0 = rb * 64;
    if (tid < 64) sU[tid] = g_U[row0 + tid];
    __syncthreads();
    const float kk = g_kscale;
    const float* cp = c + (size_t)row0 * NN + col0;
    float a0 = 0.f, a1 = 0.f, a2 = 0.f, a3 = 0.f;
#pragma unroll 4
    for (int r = 0; r < 64; ++r) {
        float4 v = *reinterpret_cast<const float4*>(cp + (size_t)r * NN);
        float u = sU[r];
        a0 = fmaf(__expf(-v.x * kk), u, a0);
        a1 = fmaf(__expf(-v.y * kk), u, a1);
        a2 = fmaf(__expf(-v.z * kk), u, a2);
        a3 = fmaf(__expf(-v.w * kk), u, a3);
    }
    float* ca = g_colAccS[rb & 3];
    atomicAdd(&ca[col0 + 0], a0);
    atomicAdd(&ca[col0 + 1], a1);
    atomicAdd(&ca[col0 + 2], a2);
    atomicAdd(&ca[col0 + 3], a3);
}

// ---------------------------------------------------------------- final: exact Q, fused U10, write T
__global__ void __launch_bounds__(256) k_final(const float* __restrict__ c,
                                               const float* __restrict__ A,
                                               float* __restrict__ out) {
    __shared__ float sV[NN];
    __shared__ float sred[8];
    __shared__ float sbc;
    int tid = threadIdx.x;
#pragma unroll
    for (int i = 0; i < 8; ++i)
        reinterpret_cast<float4*>(sV)[tid + i * 256] =
            reinterpret_cast<const float4*>(g_V)[tid + i * 256];
    __syncthreads();
    const float kk = g_kscale;
    for (int row = blockIdx.x; row < NN; row += gridDim.x) {
        const float4* crow = reinterpret_cast<const float4*>(c + (size_t)row * NN);
        float4 qv[8];
        float s = 0.f;
#pragma unroll
        for (int k = 0; k < 8; ++k) {
            int j = tid * 4 + k * 1024;
            float4 v  = crow[tid + k * 256];
            float4 vv = *reinterpret_cast<const float4*>(sV + j);
            float q0 = __expf(-v.x * kk) * vv.x;
            float q1 = __expf(-v.y * kk) * vv.y;
            float q2 = __expf(-v.z * kk) * vv.z;
            float q3 = __expf(-v.w * kk) * vv.w;
            qv[k].x = q0; qv[k].y = q1; qv[k].z = q2; qv[k].w = q3;
            s += (q0 + q1) + (q2 + q3);
        }
        for (int o = 16; o > 0; o >>= 1)
            s += __shfl_down_sync(0xffffffffu, s, o);
        if ((tid & 31) == 0) sred[tid >> 5] = s;
        __syncthreads();
        if (tid < 32) {
            float t = (tid < 8) ? sred[tid] : 0.f;
            for (int o = 4; o > 0; o >>= 1)
                t += __shfl_down_sync(0xffffffffu, t, o);
            if (tid == 0) sbc = __ldg(A + row) / t;
        }
        __syncthreads();
        float scale = sbc;
        float4* orow = reinterpret_cast<float4*>(out + (size_t)row * NN);
#pragma unroll
        for (int k = 0; k < 8; ++k) {
            float4 w = qv[k];
            w.x *= scale; w.y *= scale; w.z *= scale; w.w *= scale;
            orow[tid + k * 256] = w;
        }
        __syncthreads();
    }
}

// ---------------------------------------------------------------- launch
extern "C" void kernel_launch(void* const* d_in, const int* in_sizes, int n_in,
                              void* d_out, int out_size) {
    const float* cdist = (const float*)d_in[0];
    const float* A     = (const float*)d_in[1];
    const float* B     = (const float*)d_in[2];
    float* out = (float*)d_out;

    k_init<<<32, 256>>>();
    k_reduce<<<1184, 256>>>(cdist);          // sum/sumsq + fused kscale
    k_build8<<<dim3(8, 128), 256>>>(cdist);  // Q8 (fp8), exact colsum -> slices
    k_vfin<<<32, 256>>>(B);                  // V1
    for (int it = 1; it <= 8; ++it) {
        k_rowmv8<<<512, 256>>>(A);           // U_it = A/(Q8 V_it)
        k_colmv8<<<512, 256>>>();            // slices = Q8^T U_it
        k_vfin<<<32, 256>>>(B);              // V_{it+1}
    }
    k_rowmv8<<<512, 256>>>(A);               // U9
    k_colmv_exact<<<1024, 256>>>(cdist);     // slices = Q^T U9 (exact)
    k_vfin<<<32, 256>>>(B);                  // V10 (accurate)
    // U10 fused into output: exact fp32 Q, T = (A_i/(Q V10)_i) * Q_ij * V10_j
    k_final<<<444, 256>>>(cdist, A, out);
}

// round 7
// speedup vs baseline: 1.0978x; 1.0978x over previous
#include <cuda_runtime.h>
#include <cuda_bf16.h>
#include <cuda_fp8.h>

#define NN 8192
#define TEMPER 0.2f

// Scratch (static __device__ arrays per harness rules)
static __device__ unsigned char g_Q8[(size_t)NN * NN];  // 64 MB fp8 e4m3 Q
static __device__ float g_slice[10][2][NN];             // per-iteration col accumulators
static __device__ float g_U[NN];
static __device__ double g_sum;
static __device__ double g_sumsq;
static __device__ float g_kscale;
static __device__ unsigned int g_redCount;

// ---------------------------------------------------------------- helpers
__device__ __forceinline__ float2 f8x2_to_f2(unsigned int s) {
    __half2_raw hr = __nv_cvt_fp8x2_to_halfraw2((__nv_fp8x2_storage_t)s, __NV_E4M3);
    return __half22float2(*reinterpret_cast<__half2*>(&hr));
}

// Load V into SMEM: V = B / (slice0 + slice1), float4-vectorized, 256 threads
__device__ __forceinline__ void load_V_smem(float* sV, const float* __restrict__ B, int itSrc) {
    int tid = threadIdx.x;
    const float4* s0 = reinterpret_cast<const float4*>(g_slice[itSrc][0]);
    const float4* s1 = reinterpret_cast<const float4*>(g_slice[itSrc][1]);
    const float4* b4 = reinterpret_cast<const float4*>(B);
#pragma unroll
    for (int i = 0; i < 8; ++i) {
        int idx = tid + i * 256;
        float4 a = s0[idx];
        float4 b = s1[idx];
        float4 w = b4[idx];
        float4 v;
        v.x = w.x / (a.x + b.x);
        v.y = w.y / (a.y + b.y);
        v.z = w.z / (a.z + b.z);
        v.w = w.w / (a.w + b.w);
        reinterpret_cast<float4*>(sV)[idx] = v;
    }
}

// ---------------------------------------------------------------- init: zero slice buffers
__global__ void k_init() {
    int i = blockIdx.x * blockDim.x + threadIdx.x;
    float* p = &g_slice[0][0][0];
    int total = 10 * 2 * NN;
    for (int j = i; j < total; j += gridDim.x * blockDim.x) p[j] = 0.0f;
    if (i == 0) {
        g_sum = 0.0;
        g_sumsq = 0.0;
        g_redCount = 0u;
    }
}

// ---------------------------------------------------------------- reduce: sum / sumsq + fused scalar finalize
__global__ void __launch_bounds__(256) k_reduce(const float* __restrict__ c) {
    const size_t total4 = (size_t)NN * NN / 4;
    const size_t stride = (size_t)gridDim.x * blockDim.x;
    double s = 0.0, ss = 0.0;
    for (size_t i = (size_t)blockIdx.x * blockDim.x + threadIdx.x; i < total4; i += stride) {
        float4 v = reinterpret_cast<const float4*>(c)[i];
        float cs  = (v.x + v.y) + (v.z + v.w);
        float css = fmaf(v.x, v.x, fmaf(v.y, v.y, fmaf(v.z, v.z, v.w * v.w)));
        s  += (double)cs;
        ss += (double)css;
    }
    for (int o = 16; o > 0; o >>= 1) {
        s  += __shfl_down_sync(0xffffffffu, s, o);
        ss += __shfl_down_sync(0xffffffffu, ss, o);
    }
    __shared__ double sh_s[8], sh_ss[8];
    int warp = threadIdx.x >> 5, lane = threadIdx.x & 31;
    if (lane == 0) { sh_s[warp] = s; sh_ss[warp] = ss; }
    __syncthreads();
    if (threadIdx.x < 8) {
        s = sh_s[threadIdx.x]; ss = sh_ss[threadIdx.x];
        for (int o = 4; o > 0; o >>= 1) {
            s  += __shfl_down_sync(0xffu, s, o);
            ss += __shfl_down_sync(0xffu, ss, o);
        }
        if (threadIdx.x == 0) {
            atomicAdd(&g_sum, s);
            atomicAdd(&g_sumsq, ss);
            __threadfence();
            unsigned int done = atomicAdd(&g_redCount, 1u);
            if (done == gridDim.x - 1) {
                double n = (double)NN * (double)NN;
                double S  = *(volatile double*)&g_sum;
                double SS = *(volatile double*)&g_sumsq;
                double var = (SS - S * S / n) / (n - 1.0);
                g_kscale = 1.0f / ((float)sqrt(var) * TEMPER);
            }
        }
    }
}

// ---------------------------------------------------------------- build Q8 (fp8) + exact colsum -> slice[0]
// grid (8, 128): x = 1024-col chunk, y = 64-row chunk; 4 cols/thread
__global__ void __launch_bounds__(256) k_build8(const float* __restrict__ c) {
    const float kk = g_kscale;
    int col0 = (blockIdx.x * 256 + threadIdx.x) * 4;
    int row0 = blockIdx.y * 64;
    float a0 = 0.f, a1 = 0.f, a2 = 0.f, a3 = 0.f;
    for (int r = 0; r < 64; ++r) {
        size_t base = (size_t)(row0 + r) * NN + col0;
        float4 v = *reinterpret_cast<const float4*>(c + base);
        float q0 = __expf(-v.x * kk);
        float q1 = __expf(-v.y * kk);
        float q2 = __expf(-v.z * kk);
        float q3 = __expf(-v.w * kk);
        a0 += q0; a1 += q1; a2 += q2; a3 += q3;
        float2 p0; p0.x = q0; p0.y = q1;
        float2 p1; p1.x = q2; p1.y = q3;
        unsigned int lo = __nv_cvt_float2_to_fp8x2(p0, __NV_SATFINITE, __NV_E4M3);
        unsigned int hi = __nv_cvt_float2_to_fp8x2(p1, __NV_SATFINITE, __NV_E4M3);
        *reinterpret_cast<unsigned int*>(g_Q8 + base) = (hi << 16) | (lo & 0xffffu);
    }
    float* ca = g_slice[0][blockIdx.y & 1];
    atomicAdd(&ca[col0 + 0], a0);
    atomicAdd(&ca[col0 + 1], a1);
    atomicAdd(&ca[col0 + 2], a2);
    atomicAdd(&ca[col0 + 3], a3);
}

// ---------------------------------------------------------------- U = A / (Q8 V); V computed inline
// 512 blocks x 256 threads; warp handles 2 rows; uint loads, conflict-free float4 SMEM V
__global__ void __launch_bounds__(256) k_rowmv8(const float* __restrict__ A,
                                                const float* __restrict__ B, int itSrc) {
    __shared__ float sV[NN];
    load_V_smem(sV, B, itSrc);
    __syncthreads();
    int tid = threadIdx.x;
    int warp = tid >> 5, lane = tid & 31;
    int row0 = blockIdx.x * 16 + warp * 2;
    const unsigned int* q0 = reinterpret_cast<const unsigned int*>(g_Q8 + (size_t)row0 * NN);
    const unsigned int* q1 = reinterpret_cast<const unsigned int*>(g_Q8 + (size_t)(row0 + 1) * NN);
    const float4* v4 = reinterpret_cast<const float4*>(sV);
    float acc0 = 0.f, acc1 = 0.f;
#pragma unroll
    for (int s = 0; s < 64; s += 4) {
        unsigned int a[4], b[4];
#pragma unroll
        for (int u = 0; u < 4; ++u) {
            a[u] = q0[lane + (s + u) * 32];
            b[u] = q1[lane + (s + u) * 32];
        }
#pragma unroll
        for (int u = 0; u < 4; ++u) {
            float4 v = v4[lane + (s + u) * 32];
            float2 lo = f8x2_to_f2(a[u] & 0xffffu);
            float2 hi = f8x2_to_f2(a[u] >> 16);
            acc0 = fmaf(lo.x, v.x, acc0);
            acc0 = fmaf(lo.y, v.y, acc0);
            acc0 = fmaf(hi.x, v.z, acc0);
            acc0 = fmaf(hi.y, v.w, acc0);
            float2 lo1 = f8x2_to_f2(b[u] & 0xffffu);
            float2 hi1 = f8x2_to_f2(b[u] >> 16);
            acc1 = fmaf(lo1.x, v.x, acc1);
            acc1 = fmaf(lo1.y, v.y, acc1);
            acc1 = fmaf(hi1.x, v.z, acc1);
            acc1 = fmaf(hi1.y, v.w, acc1);
        }
    }
    for (int o = 16; o > 0; o >>= 1) {
        acc0 += __shfl_down_sync(0xffffffffu, acc0, o);
        acc1 += __shfl_down_sync(0xffffffffu, acc1, o);
    }
    if (lane == 0) {
        g_U[row0]     = __ldg(A + row0) / acc0;
        g_U[row0 + 1] = __ldg(A + row0 + 1) / acc1;
    }
}

// ---------------------------------------------------------------- slice[itDst] += Q8^T U
// grid 1024: 128 row-chunks (64 rows) x 8 col-chunks (1024 cols); 4 cols/thread (uint)
__global__ void __launch_bounds__(256) k_colmv8(int itDst) {
    __shared__ float sU[64];
    int tid = threadIdx.x;
    int rb = blockIdx.x >> 3;
    int col0 = (blockIdx.x & 7) * 1024 + tid * 4;
    int row0 = rb * 64;
    if (tid < 64) sU[tid] = g_U[row0 + tid];
    __syncthreads();
    const unsigned int* qp =
        reinterpret_cast<const unsigned int*>(g_Q8 + (size_t)row0 * NN + col0);
    float a0 = 0.f, a1 = 0.f, a2 = 0.f, a3 = 0.f;
#pragma unroll 8
    for (int r = 0; r < 64; ++r) {
        unsigned int w = qp[(size_t)r * (NN / 4)];
        float u = sU[r];
        float2 lo = f8x2_to_f2(w & 0xffffu);
        float2 hi = f8x2_to_f2(w >> 16);
        a0 = fmaf(lo.x, u, a0);
        a1 = fmaf(lo.y, u, a1);
        a2 = fmaf(hi.x, u, a2);
        a3 = fmaf(hi.y, u, a3);
    }
    float* ca = g_slice[itDst][rb & 1];
    atomicAdd(&ca[col0 + 0], a0);
    atomicAdd(&ca[col0 + 1], a1);
    atomicAdd(&ca[col0 + 2], a2);
    atomicAdd(&ca[col0 + 3], a3);
}

// ---------------------------------------------------------------- exact colmv (for V10): slice[9] += Q^T U, Q from cdist
__global__ void __launch_bounds__(256) k_colmv_exact(const float* __restrict__ c) {
    __shared__ float sU[64];
    int tid = threadIdx.x;
    int rb = blockIdx.x >> 3;
    int col0 = (blockIdx.x & 7) * 1024 + tid * 4;
    int row0 = rb * 64;
    if (tid < 64) sU[tid] = g_U[row0 + tid];
    __syncthreads();
    const float kk = g_kscale;
    const float* cp = c + (size_t)row0 * NN + col0;
    float a0 = 0.f, a1 = 0.f, a2 = 0.f, a3 = 0.f;
#pragma unroll 4
    for (int r = 0; r < 64; ++r) {
        float4 v = *reinterpret_cast<const float4*>(cp + (size_t)r * NN);
        float u = sU[r];
        a0 = fmaf(__expf(-v.x * kk), u, a0);
        a1 = fmaf(__expf(-v.y * kk), u, a1);
        a2 = fmaf(__expf(-v.z * kk), u, a2);
        a3 = fmaf(__expf(-v.w * kk), u, a3);
    }
    float* ca = g_slice[9][rb & 1];
    atomicAdd(&ca[col0 + 0], a0);
    atomicAdd(&ca[col0 + 1], a1);
    atomicAdd(&ca[col0 + 2], a2);
    atomicAdd(&ca[col0 + 3], a3);
}

// ---------------------------------------------------------------- final: exact Q, V10 inline, fused U10, write T
__global__ void __launch_bounds__(256) k_final(const float* __restrict__ c,
                                               const float* __restrict__ A,
                                               const float* __restrict__ B,
                                               float* __restrict__ out) {
    __shared__ float sV[NN];
    __shared__ float sred[8];
    __shared__ float sbc;
    int tid = threadIdx.x;
    load_V_smem(sV, B, 9);
    __syncthreads();
    const float kk = g_kscale;
    for (int row = blockIdx.x; row < NN; row += gridDim.x) {
        const float4* crow = reinterpret_cast<const float4*>(c + (size_t)row * NN);
        float4 qv[8];
        float s = 0.f;
#pragma unroll
        for (int k = 0; k < 8; ++k) {
            int j = tid * 4 + k * 1024;
            float4 v  = crow[tid + k * 256];
            float4 vv = *reinterpret_cast<const float4*>(sV + j);
            float q0 = __expf(-v.x * kk) * vv.x;
            float q1 = __expf(-v.y * kk) * vv.y;
            float q2 = __expf(-v.z * kk) * vv.z;
            float q3 = __expf(-v.w * kk) * vv.w;
            qv[k].x = q0; qv[k].y = q1; qv[k].z = q2; qv[k].w = q3;
            s += (q0 + q1) + (q2 + q3);
        }
        for (int o = 16; o > 0; o >>= 1)
            s += __shfl_down_sync(0xffffffffu, s, o);
        if ((tid & 31) == 0) sred[tid >> 5] = s;
        __syncthreads();
        if (tid < 32) {
            float t = (tid < 8) ? sred[tid] : 0.f;
            for (int o = 4; o > 0; o >>= 1)
                t += __shfl_down_sync(0xffffffffu, t, o);
            if (tid == 0) sbc = __ldg(A + row) / t;
        }
        __syncthreads();
        float scale = sbc;
        float4* orow = reinterpret_cast<float4*>(out + (size_t)row * NN);
#pragma unroll
        for (int k = 0; k < 8; ++k) {
            float4 w = qv[k];
            w.x *= scale; w.y *= scale; w.z *= scale; w.w *= scale;
            orow[tid + k * 256] = w;
        }
        __syncthreads();
    }
}

// ---------------------------------------------------------------- launch
extern "C" void kernel_launch(void* const* d_in, const int* in_sizes, int n_in,
                              void* d_out, int out_size) {
    const float* cdist = (const float*)d_in[0];
    const float* A     = (const float*)d_in[1];
    const float* B     = (const float*)d_in[2];
    float* out = (float*)d_out;

    k_init<<<64, 256>>>();                    // zero slice buffers
    k_reduce<<<1184, 256>>>(cdist);           // sum/sumsq + fused kscale
    k_build8<<<dim3(8, 128), 256>>>(cdist);   // Q8 (fp8), exact colsum -> slice[0]
    for (int it = 1; it <= 8; ++it) {
        k_rowmv8<<<512, 256>>>(A, B, it - 1); // V_it inline; U_it = A/(Q8 V_it)
        k_colmv8<<<1024, 256>>>(it);          // slice[it] = Q8^T U_it
    }
    k_rowmv8<<<512, 256>>>(A, B, 8);          // U9
    k_colmv_exact<<<1024, 256>>>(cdist);      // slice[9] = Q^T U9 (exact)
    // U10 fused into output: exact fp32 Q, V10 from slice[9], T out
    k_final<<<444, 256>>>(cdist, A, B, out);
}